// round 7
// baseline (speedup 1.0000x reference)
#include <cuda_runtime.h>
#include <cuda_bf16.h>
#include <cstdint>

// ---------------------------------------------------------------------------
// Pipeline:
//   S : x -> bf16 hi/lo (fc11 A) + int8 a1/a2 (fc12 A)   [M,128] / [M,192]
//   P1: split W11 (hi|hi|lo) bf16                         -> g_B11 [128,384]
//   Pq: fold plane-stress D into W12, per-row int8 quant  -> g_Bq [384,384], g_Bsc
//   A : fc11 mma.sync bf16-split GEMM + dnew              -> g_dnew [M,64]
//   B : prefix-max over T -> dmg, int8 quant into g_Aq1/2 cols 128..191
//   C : fc12 IMMA s8 GEMM (hi K=192 + mid K=384) + seq    -> g_strain, g_seq
//   E : J2 plasticity scan                                -> g_scale
//   F : fc2 + softplus                                    -> out
// ---------------------------------------------------------------------------

typedef unsigned long long u64;

#define MM 131072   // 256*512

__device__ __align__(16) float g_dnew[(size_t)MM * 64];
__device__ __align__(16) float g_strain[(size_t)MM * 384];
__device__ __align__(16) float g_seq[(size_t)MM * 128];
__device__ __align__(16) float g_scale[(size_t)MM * 128];
__device__ __align__(16) __nv_bfloat16 g_Ah[(size_t)MM * 128];
__device__ __align__(16) __nv_bfloat16 g_Al[(size_t)MM * 128];
__device__ __align__(16) __nv_bfloat16 g_B11[128 * 384];
__device__ __align__(16) signed char g_Aq1[(size_t)MM * 192];
__device__ __align__(16) signed char g_Aq2[(size_t)MM * 192];
__device__ __align__(16) signed char g_Bq[384 * 384];
__device__ float g_Bsc[384];

__device__ __forceinline__ uint32_t smem_u32(const void* p) {
    uint32_t a;
    asm("{ .reg .u64 t; cvta.to.shared.u64 t, %1; cvt.u32.u64 %0, t; }" : "=r"(a) : "l"(p));
    return a;
}
__device__ __forceinline__ void cpasync16(uint32_t dst, const void* src) {
    asm volatile("cp.async.ca.shared.global [%0], [%1], 16;" :: "r"(dst), "l"(src) : "memory");
}
__device__ __forceinline__ void cpcommit() {
    asm volatile("cp.async.commit_group;" ::: "memory");
}
template <int N>
__device__ __forceinline__ void cpwait() {
    asm volatile("cp.async.wait_group %0;" :: "n"(N) : "memory");
}
__device__ __forceinline__ void ldsm_x4(uint32_t& r0, uint32_t& r1, uint32_t& r2,
                                        uint32_t& r3, uint32_t addr) {
    asm volatile("ldmatrix.sync.aligned.m8n8.x4.shared.b16 {%0,%1,%2,%3}, [%4];"
                 : "=r"(r0), "=r"(r1), "=r"(r2), "=r"(r3) : "r"(addr));
}
__device__ __forceinline__ void mma16816(float& c0, float& c1, float& c2, float& c3,
                                         uint32_t a0, uint32_t a1, uint32_t a2, uint32_t a3,
                                         uint32_t b0, uint32_t b1) {
    asm volatile("mma.sync.aligned.m16n8k16.row.col.f32.bf16.bf16.f32 "
                 "{%0,%1,%2,%3}, {%4,%5,%6,%7}, {%8,%9}, {%0,%1,%2,%3};"
                 : "+f"(c0), "+f"(c1), "+f"(c2), "+f"(c3)
                 : "r"(a0), "r"(a1), "r"(a2), "r"(a3), "r"(b0), "r"(b1));
}
__device__ __forceinline__ void imma16832(int& c0, int& c1, int& c2, int& c3,
                                          uint32_t a0, uint32_t a1, uint32_t a2, uint32_t a3,
                                          uint32_t b0, uint32_t b1) {
    asm volatile("mma.sync.aligned.m16n8k32.row.col.s32.s8.s8.s32 "
                 "{%0,%1,%2,%3}, {%4,%5,%6,%7}, {%8,%9}, {%0,%1,%2,%3};"
                 : "+r"(c0), "+r"(c1), "+r"(c2), "+r"(c3)
                 : "r"(a0), "r"(a1), "r"(a2), "r"(a3), "r"(b0), "r"(b1));
}
__device__ __forceinline__ signed char q8(float v) {
    int i = __float2int_rn(v);
    i = i > 127 ? 127 : (i < -127 ? -127 : i);
    return (signed char)i;
}

#define APITCH 80   // smem row pitch for 64B-data rows

// ---------------------------------------------------------------------------
// Kernel S: x -> bf16 hi/lo [M,128] + int8 a1/a2 (Δ1=2^-4, Δ2=2^-11)
// ---------------------------------------------------------------------------
__global__ void k_splitx(const float* __restrict__ x)
{
    int idx = blockIdx.x * 256 + threadIdx.x;     // 0 .. MM*32-1
    int m = idx >> 5, q = (idx & 31) << 2;
    float4 v = *(const float4*)(x + (size_t)m * 128 + q);
    float f[4] = {v.x, v.y, v.z, v.w};
    __nv_bfloat16 h[4], l[4];
    signed char a1[4], a2[4];
#pragma unroll
    for (int i = 0; i < 4; ++i) {
        h[i] = __float2bfloat16(f[i]);
        l[i] = __float2bfloat16(f[i] - __bfloat162float(h[i]));
        int q1 = __float2int_rn(f[i] * 16.f);
        q1 = q1 > 127 ? 127 : (q1 < -127 ? -127 : q1);
        a1[i] = (signed char)q1;
        float r = f[i] - q1 * 0.0625f;
        a2[i] = q8(r * 2048.f);
    }
    *(u64*)(g_Ah + (size_t)m * 128 + q) = *(u64*)h;
    *(u64*)(g_Al + (size_t)m * 128 + q) = *(u64*)l;
    *(uint32_t*)(g_Aq1 + (size_t)m * 192 + q) = *(uint32_t*)a1;
    *(uint32_t*)(g_Aq2 + (size_t)m * 192 + q) = *(uint32_t*)a2;
}

// ---------------------------------------------------------------------------
// Kernel P1: split W11 -> g_B11 [128,384]: [0,128)=hi, [128,256)=hi, [256,384)=lo
// ---------------------------------------------------------------------------
__global__ void k_prepB11(const float* __restrict__ W11)
{
    int t = blockIdx.x * 256 + threadIdx.x;
    if (t >= 128 * 128) return;
    int n = t >> 7, k = t & 127;
    float w = W11[(size_t)n * 128 + k];
    __nv_bfloat16 hi = __float2bfloat16(w);
    float lo = w - __bfloat162float(hi);
    g_B11[(size_t)n * 384 + k]       = hi;
    g_B11[(size_t)n * 384 + 128 + k] = hi;
    g_B11[(size_t)n * 384 + 256 + k] = __float2bfloat16(lo);
}

// ---------------------------------------------------------------------------
// Kernel Pq: fold plane-stress D into W12, per-row pow2 scale int8 quant.
//   g_Bq[n][0..191] = w1 (scale d1[n]); g_Bq[n][192..383] = w2 (scale d1/128)
//   g_Bsc[n] = d1[n] * 2^-4  (A-scale folded in)
//   one warp per n.
// ---------------------------------------------------------------------------
__global__ void k_prepBq(const float* __restrict__ W12)
{
    int n = blockIdx.x * 8 + (threadIdx.x >> 5);
    int lane = threadIdx.x & 31;
    int p3 = (n / 3) * 3, j = n % 3;
    const float C   = 1098.9010989010989f;
    const float CNU = 329.67032967032966f;
    const float CSH = 384.61538461538464f;
    float w[6];
#pragma unroll
    for (int i = 0; i < 6; ++i) {
        int k = lane + 32 * i;
        if (j == 0)      w[i] = C   * W12[(size_t)p3 * 192 + k] + CNU * W12[(size_t)(p3 + 1) * 192 + k];
        else if (j == 1) w[i] = CNU * W12[(size_t)p3 * 192 + k] + C   * W12[(size_t)(p3 + 1) * 192 + k];
        else             w[i] = CSH * W12[(size_t)n * 192 + k];
    }
    float mx = 0.f;
#pragma unroll
    for (int i = 0; i < 6; ++i) mx = fmaxf(mx, fabsf(w[i]));
#pragma unroll
    for (int off = 16; off; off >>= 1)
        mx = fmaxf(mx, __shfl_xor_sync(0xffffffffu, mx, off));
    int e;
    frexpf(mx * (1.f / 127.f) + 1e-30f, &e);
    float d1 = ldexpf(1.f, e);
    float inv1 = 1.f / d1;
#pragma unroll
    for (int i = 0; i < 6; ++i) {
        int k = lane + 32 * i;
        float w1 = rintf(w[i] * inv1);
        w1 = fminf(fmaxf(w1, -127.f), 127.f);
        float r = w[i] - w1 * d1;
        g_Bq[(size_t)n * 384 + k]       = (signed char)(int)w1;
        g_Bq[(size_t)n * 384 + 192 + k] = q8(r * 128.f * inv1);
    }
    if (lane == 0) g_Bsc[n] = d1 * 0.0625f;
}

// ---------------------------------------------------------------------------
// Kernel A: fc11 bf16-split mma.sync GEMM (R5 structure, fixed last-stage wait)
//   grid (1024,2), BM=128, BN=64, K'=384 (12 stages of Kc=32), 3-stage cp.async
// ---------------------------------------------------------------------------
#define FC11_STAGE 15360
#define FC11_SMEM  46080

__global__ void __launch_bounds__(256, 2) k_fc11_mma(const float* __restrict__ b11)
{
    extern __shared__ char smem[];
    const uint32_t sb = smem_u32(smem);
    const int tid  = threadIdx.x;
    const int lane = tid & 31;
    const int w    = tid >> 5;
    const int wm   = w >> 1;
    const int wn   = w & 1;
    const int g    = lane >> 2;
    const int t4   = lane & 3;
    const int m0   = blockIdx.x << 7;
    const int n0   = blockIdx.y << 6;

    __shared__ float b11s[128];
    if (tid < 128) b11s[tid] = b11[tid];

    float acc[2][4][4];
#pragma unroll
    for (int a = 0; a < 2; ++a)
#pragma unroll
        for (int b = 0; b < 4; ++b)
#pragma unroll
            for (int c = 0; c < 4; ++c) acc[a][b][c] = 0.f;

    const int lrow = tid >> 2, lch = tid & 3;

    auto issue = [&](int s) {
        const int seg = s >> 2;                 // 0:hi 1:lo 2:hi
        const int kk0 = (s & 3) << 5;
        const __nv_bfloat16* Asrc = (seg == 1) ? g_Al : g_Ah;
        uint32_t base = sb + (uint32_t)(s % 3) * FC11_STAGE;
#pragma unroll
        for (int i = 0; i < 2; ++i) {
            int row = lrow + (i << 6);
            cpasync16(base + row * APITCH + (lch << 4),
                      Asrc + (size_t)(m0 + row) * 128 + kk0 + (lch << 3));
        }
        cpasync16(base + 10240 + lrow * APITCH + (lch << 4),
                  g_B11 + (size_t)(n0 + lrow) * 384 + (s << 5) + (lch << 3));
        cpcommit();
    };

    issue(0); issue(1);

    for (int s = 0; s < 12; ++s) {
        if (s < 11) { cpwait<1>(); } else { cpwait<0>(); }
        __syncthreads();
        if (s + 2 < 12) issue(s + 2);

        const uint32_t Ab = sb + (uint32_t)(s % 3) * FC11_STAGE;
        const uint32_t Bb = Ab + 10240u;
#pragma unroll
        for (int ks = 0; ks < 2; ++ks) {
            const int kk = ks << 4;
            uint32_t a[2][4];
#pragma unroll
            for (int mt = 0; mt < 2; ++mt) {
                int row = wm * 32 + mt * 16 + (lane & 15);
                ldsm_x4(a[mt][0], a[mt][1], a[mt][2], a[mt][3],
                        Ab + row * APITCH + ((kk + ((lane >> 4) << 3)) << 1));
            }
#pragma unroll
            for (int np = 0; np < 2; ++np) {
                int n = wn * 32 + np * 16 + ((lane >> 4) << 3) + (lane & 7);
                uint32_t b0, b1, b2, b3;
                ldsm_x4(b0, b1, b2, b3, Bb + n * APITCH + ((kk + (lane & 8)) << 1));
#pragma unroll
                for (int mt = 0; mt < 2; ++mt) {
                    mma16816(acc[mt][2*np][0], acc[mt][2*np][1], acc[mt][2*np][2], acc[mt][2*np][3],
                             a[mt][0], a[mt][1], a[mt][2], a[mt][3], b0, b1);
                    mma16816(acc[mt][2*np+1][0], acc[mt][2*np+1][1], acc[mt][2*np+1][2], acc[mt][2*np+1][3],
                             a[mt][0], a[mt][1], a[mt][2], a[mt][3], b2, b3);
                }
            }
        }
    }

#pragma unroll
    for (int mt = 0; mt < 2; ++mt)
#pragma unroll
        for (int nn = 0; nn < 4; ++nn) {
            int n = n0 + wn * 32 + (nn >> 1) * 16 + (nn & 1) * 8 + 2 * t4;
            float be = b11s[n], bo = b11s[n + 1];
            int r0 = m0 + wm * 32 + mt * 16 + g;
#pragma unroll
            for (int hh = 0; hh < 2; ++hh) {
                float v0 = acc[mt][nn][2 * hh]     + be;
                float v1 = acc[mt][nn][2 * hh + 1] + bo;
                v0 = v0 > 0.f ? v0 : 0.01f * v0;
                v1 = v1 > 0.f ? v1 : 0.01f * v1;
                float jn = fmaxf(v0, 0.f);
                float delta = sqrtf(jn * jn + v1 * v1 + 1e-12f);
                float dn = __fdividef(0.1f * (delta - 0.01f),
                                      fmaxf(delta, 1e-12f) * 0.09f);
                dn = fminf(fmaxf(dn, 0.f), 1.f);
                g_dnew[(size_t)(r0 + 8 * hh) * 64 + (n >> 1)] = dn;
            }
        }
}

// ---------------------------------------------------------------------------
// Kernel B: prefix-max of dnew over T -> dmg int8 (a1/a2) into cols 128..191
// ---------------------------------------------------------------------------
__global__ void k_prefixmax()
{
    int t = blockIdx.x * blockDim.x + threadIdx.x;   // 0..16383
    int b = t >> 6, p = t & 63;
    const float* src = g_dnew + (size_t)b * 512 * 64 + p;
    signed char* d1 = g_Aq1 + (size_t)b * 512 * 192 + 128 + p;
    signed char* d2 = g_Aq2 + (size_t)b * 512 * 192 + 128 + p;
    float run = 0.f;
    for (int t0 = 0; t0 < 512; t0 += 8) {
        float v[8];
#pragma unroll
        for (int i = 0; i < 8; ++i) v[i] = src[(size_t)(t0 + i) * 64];
#pragma unroll
        for (int i = 0; i < 8; ++i) {
            run = fmaxf(run, v[i]);
            int q1 = __float2int_rn(run * 16.f);
            float r = run - q1 * 0.0625f;
            d1[(size_t)(t0 + i) * 192] = (signed char)q1;
            d2[(size_t)(t0 + i) * 192] = q8(r * 2048.f);
        }
    }
}

// ---------------------------------------------------------------------------
// Kernel C: fc12 via IMMA s8. grid (1024,4): BM=128, BN=96.
//   9 stages of Kc=64: [A1xW1]x3 (acc_hi), [A2xW1]x3 + [A1xW2]x3 (acc_mid).
//   strain = g_Bsc[n] * (hi + mid/128). 3-stage cp.async, 256 thr, warp 32x48.
// ---------------------------------------------------------------------------
#define FC12_STG  17920
#define FC12_SMEM 53760

__global__ void __launch_bounds__(256, 1) k_fc12_i8()
{
    extern __shared__ char smem[];
    const uint32_t sb = smem_u32(smem);
    const int tid  = threadIdx.x;
    const int lane = tid & 31;
    const int w    = tid >> 5;
    const int wm   = w >> 1;
    const int wn   = w & 1;
    const int g    = lane >> 2;
    const int t4   = lane & 3;
    const int m0   = blockIdx.x << 7;
    const int gy   = blockIdx.y;

    int acc_hi[2][6][4], acc_mid[2][6][4];
#pragma unroll
    for (int a = 0; a < 2; ++a)
#pragma unroll
        for (int b = 0; b < 6; ++b)
#pragma unroll
            for (int c = 0; c < 4; ++c) { acc_hi[a][b][c] = 0; acc_mid[a][b][c] = 0; }

    auto issue = [&](int s) {
        const signed char* Aplane = (s >= 3 && s < 6) ? g_Aq2 : g_Aq1;
        const int acol = (s % 3) << 6;
        const int bcol = (s < 6) ? ((s % 3) << 6) : (192 + ((s % 3) << 6));
        uint32_t base = sb + (uint32_t)(s % 3) * FC12_STG;
#pragma unroll
        for (int i = 0; i < 2; ++i) {
            int id = tid + (i << 8);
            int row = id >> 2, c = id & 3;
            cpasync16(base + row * APITCH + (c << 4),
                      Aplane + (size_t)(m0 + row) * 192 + acol + (c << 4));
        }
#pragma unroll
        for (int i = 0; i < 2; ++i) {
            int id = tid + (i << 8);
            if (id < 384) {
                int row = id >> 2, c = id & 3;
                cpasync16(base + 10240 + row * APITCH + (c << 4),
                          g_Bq + (size_t)(gy * 96 + row) * 384 + bcol + (c << 4));
            }
        }
        cpcommit();
    };

    issue(0); issue(1);

#define FC12_STAGE_BODY(S, ACC) do {                                            \
    if ((S) < 8) { cpwait<1>(); } else { cpwait<0>(); }                         \
    __syncthreads();                                                            \
    if ((S) + 2 < 9) issue((S) + 2);                                            \
    const uint32_t Ab = sb + (uint32_t)((S) % 3) * FC12_STG;                    \
    const uint32_t Bb = Ab + 10240u;                                            \
    _Pragma("unroll")                                                           \
    for (int j = 0; j < 2; ++j) {                                               \
        uint32_t a[2][4];                                                       \
        _Pragma("unroll")                                                       \
        for (int mt = 0; mt < 2; ++mt) {                                        \
            int row = wm * 32 + mt * 16 + (lane & 15);                          \
            ldsm_x4(a[mt][0], a[mt][1], a[mt][2], a[mt][3],                     \
                    Ab + row * APITCH + (j << 5) + ((lane >> 4) << 4));         \
        }                                                                       \
        _Pragma("unroll")                                                       \
        for (int q = 0; q < 3; ++q) {                                           \
            int n = wn * 48 + q * 16 + (lane & 7) + ((lane >> 4) << 3);         \
            uint32_t b0, b1, b2, b3;                                            \
            ldsm_x4(b0, b1, b2, b3,                                             \
                    Bb + n * APITCH + (j << 5) + (((lane >> 3) & 1) << 4));     \
            _Pragma("unroll")                                                   \
            for (int mt = 0; mt < 2; ++mt) {                                    \
                imma16832(ACC[mt][2*q][0], ACC[mt][2*q][1], ACC[mt][2*q][2],    \
                          ACC[mt][2*q][3], a[mt][0], a[mt][1], a[mt][2],        \
                          a[mt][3], b0, b1);                                    \
                imma16832(ACC[mt][2*q+1][0], ACC[mt][2*q+1][1],                 \
                          ACC[mt][2*q+1][2], ACC[mt][2*q+1][3],                 \
                          a[mt][0], a[mt][1], a[mt][2], a[mt][3], b2, b3);      \
            }                                                                   \
        }                                                                       \
    }                                                                           \
} while (0)

    for (int s = 0; s < 3; ++s) FC12_STAGE_BODY(s, acc_hi);
    for (int s = 3; s < 9; ++s) FC12_STAGE_BODY(s, acc_mid);
#undef FC12_STAGE_BODY

    // ---------------- epilogue: combine, scale, seq, store ----------------
    __syncthreads();
    const int cb  = gy * 96 + wn * 48;
    float* slab = (float*)smem + w * 1664;     // 32 x 52 floats per warp
#pragma unroll
    for (int mt = 0; mt < 2; ++mt)
#pragma unroll
        for (int nn = 0; nn < 6; ++nn) {
            int col = nn * 8 + 2 * t4;
            float s0 = g_Bsc[cb + col];
            float s1 = g_Bsc[cb + col + 1];
            int row = mt * 16 + g;
            slab[row * 52 + col]           = s0 * ((float)acc_hi[mt][nn][0] + (float)acc_mid[mt][nn][0] * 0.0078125f);
            slab[row * 52 + col + 1]       = s1 * ((float)acc_hi[mt][nn][1] + (float)acc_mid[mt][nn][1] * 0.0078125f);
            slab[(row + 8) * 52 + col]     = s0 * ((float)acc_hi[mt][nn][2] + (float)acc_mid[mt][nn][2] * 0.0078125f);
            slab[(row + 8) * 52 + col + 1] = s1 * ((float)acc_hi[mt][nn][3] + (float)acc_mid[mt][nn][3] * 0.0078125f);
        }
    __syncwarp();

    const int mbase = m0 + wm * 32;
    const int pbi = gy * 32 + wn * 16;
#pragma unroll 1
    for (int r = 0; r < 32; ++r) {
        if (lane < 16) {
            float s0 = slab[r * 52 + 3 * lane];
            float s1 = slab[r * 52 + 3 * lane + 1];
            float s2 = slab[r * 52 + 3 * lane + 2];
            float seq = sqrtf(s0 * s0 - s0 * s1 + s1 * s1 + 3.f * s2 * s2 + 1e-12f);
            g_seq[(size_t)(mbase + r) * 128 + pbi + lane] = seq;
        }
        if (lane < 12) {
            float4 v = *(float4*)&slab[r * 52 + 4 * lane];
            *(float4*)&g_strain[(size_t)(mbase + r) * 384 + cb - wn * 48 + wn * 48 + 4 * lane] = v;
        }
    }
}

// ---------------------------------------------------------------------------
// Kernel E: J2 radial-return ep chains
// ---------------------------------------------------------------------------
__global__ void k_ep()
{
    int t = blockIdx.x * 256 + threadIdx.x;
    int b = t >> 7, p = t & 127;
    const float* sq = g_seq   + (size_t)b * 512 * 128 + p;
    float*       sc = g_scale + (size_t)b * 512 * 128 + p;
    const float SY = 10.f, H = 100.f;
    const float INV = (float)(1.0 / (3.0 * (1000.0 / 2.6) + 100.0));
    float ep = 0.f;
    for (int t0 = 0; t0 < 512; t0 += 8) {
        float v[8];
#pragma unroll
        for (int i = 0; i < 8; ++i) v[i] = sq[(size_t)(t0 + i) * 128];
        float out[8];
#pragma unroll
        for (int i = 0; i < 8; ++i) {
            float fy = v[i] - fmaf(H, ep, SY);
            if (fy > 0.f) {
                ep = fmaf(fy, INV, ep);
                out[i] = __fdividef(fmaf(H, ep, SY), v[i]);
            } else {
                out[i] = 1.f;
            }
        }
#pragma unroll
        for (int i = 0; i < 8; ++i) sc[(size_t)(t0 + i) * 128] = out[i];
    }
}

// ---------------------------------------------------------------------------
// Kernel F: fc2 + softplus
// ---------------------------------------------------------------------------
__global__ void k_fc2(const float* __restrict__ W2, float* __restrict__ out)
{
    __shared__ float w2s[6 * 384];
    int tid = threadIdx.x;
    for (int i = tid; i < 2304; i += 256) w2s[i] = W2[i];
    __syncthreads();

    int warp = tid >> 5, lane = tid & 31;
    int m = blockIdx.x * 8 + warp;
    const float* sig = g_strain + (size_t)m * 384;
    const float* scl = g_scale  + (size_t)m * 128;
    float acc[6] = {0.f, 0.f, 0.f, 0.f, 0.f, 0.f};
#pragma unroll
    for (int q = 0; q < 4; ++q) {
        int p = lane + 32 * q;
        float s = scl[p];
        float f0 = sig[3 * p], f1 = sig[3 * p + 1], f2 = sig[3 * p + 2];
        float g0 = s * f0, g1 = s * f1, g2 = s * f2;
#pragma unroll
        for (int o = 0; o < 6; ++o) {
            acc[o] = fmaf(g0, w2s[o * 384 + 3 * p],     acc[o]);
            acc[o] = fmaf(g1, w2s[o * 384 + 3 * p + 1], acc[o]);
            acc[o] = fmaf(g2, w2s[o * 384 + 3 * p + 2], acc[o]);
        }
    }
#pragma unroll
    for (int o = 0; o < 6; ++o)
#pragma unroll
        for (int off = 16; off; off >>= 1)
            acc[o] += __shfl_xor_sync(0xffffffffu, acc[o], off);
    if (lane == 0) {
#pragma unroll
        for (int o = 0; o < 6; ++o) {
            float v = acc[o];
            float sp = fmaxf(v, 0.f) + log1pf(expf(-fabsf(v)));
            out[(size_t)m * 6 + o] = sp;
        }
    }
}

// ---------------------------------------------------------------------------
extern "C" void kernel_launch(void* const* d_in, const int* in_sizes, int n_in,
                              void* d_out, int out_size)
{
    const float* x   = (const float*)d_in[0];
    const float* W11 = (const float*)d_in[1];
    const float* b11 = (const float*)d_in[2];
    const float* W12 = (const float*)d_in[3];
    const float* W2  = (const float*)d_in[4];
    float* out = (float*)d_out;

    (void)in_sizes; (void)n_in; (void)out_size;

    cudaFuncSetAttribute(k_fc11_mma, cudaFuncAttributeMaxDynamicSharedMemorySize, FC11_SMEM);
    cudaFuncSetAttribute(k_fc12_i8,  cudaFuncAttributeMaxDynamicSharedMemorySize, FC12_SMEM);

    k_splitx<<<MM / 8, 256>>>(x);
    k_prepB11<<<64, 256>>>(W11);
    k_prepBq<<<48, 256>>>(W12);
    k_fc11_mma<<<dim3(MM / 128, 2), 256, FC11_SMEM>>>(b11);
    k_prefixmax<<<64, 256>>>();
    k_fc12_i8<<<dim3(MM / 128, 4), 256, FC12_SMEM>>>();
    k_ep<<<128, 256>>>();
    k_fc2<<<MM / 8, 256>>>(W2, out);
}

// round 8
// speedup vs baseline: 1.3788x; 1.3788x over previous
#include <cuda_runtime.h>
#include <cuda_bf16.h>
#include <cstdint>

// ---------------------------------------------------------------------------
// Pipeline (all-bf16-split, fat warp tiles):
//   S : split x -> bf16 hi/lo            -> g_Ah/g_Al [M,192] cols 0..127
//   P1: split W11 (hi|hi|lo)             -> g_B11 [128,384] bf16
//   P2: fold plane-stress D into W12, split -> g_Bp [384,576] bf16
//   A : fc11 mma.sync GEMM + dnew        -> g_dnew  [M,64]   (warp tile 64x32)
//   B : prefix-max over T -> dmg hi/lo   -> g_Ah/g_Al cols 128..191
//   C : fc12 mma.sync GEMM + seq         -> g_strain, g_seq  (warp tile 64x48)
//   E : J2 plasticity scan               -> g_scale
//   F : fc2 + softplus                   -> out
// R8 change: warp tiles 2x taller (64 rows) -> ldsm bytes per MAC drops
// ~40%; GEMMs were LDSM-BW-bound (L1 77%, tensor pinned 33%).
// ---------------------------------------------------------------------------

typedef unsigned long long u64;

#define MM 131072   // 256*512

__device__ __align__(16) float g_dnew[(size_t)MM * 64];
__device__ __align__(16) float g_strain[(size_t)MM * 384];
__device__ __align__(16) float g_seq[(size_t)MM * 128];
__device__ __align__(16) float g_scale[(size_t)MM * 128];
__device__ __align__(16) __nv_bfloat16 g_Ah[(size_t)MM * 192];
__device__ __align__(16) __nv_bfloat16 g_Al[(size_t)MM * 192];
__device__ __align__(16) __nv_bfloat16 g_Bp[384 * 576];
__device__ __align__(16) __nv_bfloat16 g_B11[128 * 384];

__device__ __forceinline__ uint32_t smem_u32(const void* p) {
    uint32_t a;
    asm("{ .reg .u64 t; cvta.to.shared.u64 t, %1; cvt.u32.u64 %0, t; }" : "=r"(a) : "l"(p));
    return a;
}
__device__ __forceinline__ void cpasync16(uint32_t dst, const void* src) {
    asm volatile("cp.async.ca.shared.global [%0], [%1], 16;" :: "r"(dst), "l"(src) : "memory");
}
__device__ __forceinline__ void cpcommit() {
    asm volatile("cp.async.commit_group;" ::: "memory");
}
template <int N>
__device__ __forceinline__ void cpwait() {
    asm volatile("cp.async.wait_group %0;" :: "n"(N) : "memory");
}
__device__ __forceinline__ void ldsm_x4(uint32_t& r0, uint32_t& r1, uint32_t& r2,
                                        uint32_t& r3, uint32_t addr) {
    asm volatile("ldmatrix.sync.aligned.m8n8.x4.shared.b16 {%0,%1,%2,%3}, [%4];"
                 : "=r"(r0), "=r"(r1), "=r"(r2), "=r"(r3) : "r"(addr));
}
__device__ __forceinline__ void mma16816(float& c0, float& c1, float& c2, float& c3,
                                         uint32_t a0, uint32_t a1, uint32_t a2, uint32_t a3,
                                         uint32_t b0, uint32_t b1) {
    asm volatile("mma.sync.aligned.m16n8k16.row.col.f32.bf16.bf16.f32 "
                 "{%0,%1,%2,%3}, {%4,%5,%6,%7}, {%8,%9}, {%0,%1,%2,%3};"
                 : "+f"(c0), "+f"(c1), "+f"(c2), "+f"(c3)
                 : "r"(a0), "r"(a1), "r"(a2), "r"(a3), "r"(b0), "r"(b1));
}

#define APITCH 80   // smem row pitch: 64B data + 16B pad (conflict-free ldsm)

// ---------------------------------------------------------------------------
// Kernel S: split x into bf16 hi/lo -> g_Ah/g_Al cols [0,128)
// ---------------------------------------------------------------------------
__global__ void k_splitx(const float* __restrict__ x)
{
    int idx = blockIdx.x * 256 + threadIdx.x;     // 0 .. MM*32-1
    int m = idx >> 5, q = (idx & 31) << 2;
    float4 v = *(const float4*)(x + (size_t)m * 128 + q);
    __nv_bfloat16 h[4], l[4];
    float f[4] = {v.x, v.y, v.z, v.w};
#pragma unroll
    for (int i = 0; i < 4; ++i) {
        h[i] = __float2bfloat16(f[i]);
        l[i] = __float2bfloat16(f[i] - __bfloat162float(h[i]));
    }
    *(u64*)(g_Ah + (size_t)m * 192 + q) = *(u64*)h;
    *(u64*)(g_Al + (size_t)m * 192 + q) = *(u64*)l;
}

// ---------------------------------------------------------------------------
// Kernel P1: split W11 -> g_B11 [128,384]: [0,128)=hi, [128,256)=hi, [256,384)=lo
// ---------------------------------------------------------------------------
__global__ void k_prepB11(const float* __restrict__ W11)
{
    int t = blockIdx.x * 256 + threadIdx.x;
    if (t >= 128 * 128) return;
    int n = t >> 7, k = t & 127;
    float w = W11[(size_t)n * 128 + k];
    __nv_bfloat16 hi = __float2bfloat16(w);
    float lo = w - __bfloat162float(hi);
    g_B11[(size_t)n * 384 + k]       = hi;
    g_B11[(size_t)n * 384 + 128 + k] = hi;
    g_B11[(size_t)n * 384 + 256 + k] = __float2bfloat16(lo);
}

// ---------------------------------------------------------------------------
// Kernel P2: fold plane-stress D into W12, split -> g_Bp [384,576]
// ---------------------------------------------------------------------------
__global__ void k_prepB(const float* __restrict__ W12)
{
    int t = blockIdx.x * 256 + threadIdx.x;
    if (t >= 384 * 192) return;
    int n = t / 192, k = t % 192;
    int p3 = (n / 3) * 3, j = n % 3;
    const float C   = 1098.9010989010989f;   // E/(1-nu^2)
    const float CNU = 329.67032967032966f;   // C*nu
    const float CSH = 384.61538461538464f;   // C*(1-nu)/2
    float w;
    if (j == 0)      w = C   * W12[(size_t)p3 * 192 + k] + CNU * W12[(size_t)(p3 + 1) * 192 + k];
    else if (j == 1) w = CNU * W12[(size_t)p3 * 192 + k] + C   * W12[(size_t)(p3 + 1) * 192 + k];
    else             w = CSH * W12[(size_t)n * 192 + k];
    __nv_bfloat16 hi = __float2bfloat16(w);
    float lo = w - __bfloat162float(hi);
    g_Bp[(size_t)n * 576 + k]       = hi;
    g_Bp[(size_t)n * 576 + 192 + k] = hi;
    g_Bp[(size_t)n * 576 + 384 + k] = __float2bfloat16(lo);
}

// ---------------------------------------------------------------------------
// Kernel A: fc11 mma.sync GEMM. grid (1024): BM=128, BN=128, K'=384.
//   8 warps as 2M x 4N -> warp tile 64x32, acc[4][4][4].
//   12 stages Kc=32, 3-stage cp.async (20480 B/stage, 61440 total).
// ---------------------------------------------------------------------------
#define FC11_STG  20480
#define FC11_SMEM 61440

__global__ void __launch_bounds__(256, 1) k_fc11_mma(const float* __restrict__ b11)
{
    extern __shared__ char smem[];
    const uint32_t sb = smem_u32(smem);
    const int tid  = threadIdx.x;
    const int lane = tid & 31;
    const int w    = tid >> 5;
    const int wm   = w >> 2;            // 0..1
    const int wn   = w & 3;             // 0..3
    const int g    = lane >> 2;
    const int t4   = lane & 3;
    const int m0   = blockIdx.x << 7;

    __shared__ float b11s[128];
    if (tid < 128) b11s[tid] = b11[tid];

    float acc[4][4][4];
#pragma unroll
    for (int a = 0; a < 4; ++a)
#pragma unroll
        for (int b = 0; b < 4; ++b)
#pragma unroll
            for (int c = 0; c < 4; ++c) acc[a][b][c] = 0.f;

    const int lrow = tid >> 2, lch = tid & 3;

    auto issue = [&](int s) {
        const int seg = s >> 2;                 // 0:hi 1:lo 2:hi
        const int kk0 = (s & 3) << 5;
        const __nv_bfloat16* Asrc = (seg == 1) ? g_Al : g_Ah;
        uint32_t base = sb + (uint32_t)(s % 3) * FC11_STG;
#pragma unroll
        for (int i = 0; i < 2; ++i) {
            int row = lrow + (i << 6);
            cpasync16(base + row * APITCH + (lch << 4),
                      Asrc + (size_t)(m0 + row) * 192 + kk0 + (lch << 3));
        }
#pragma unroll
        for (int i = 0; i < 2; ++i) {
            int row = lrow + (i << 6);
            cpasync16(base + 10240 + row * APITCH + (lch << 4),
                      g_B11 + (size_t)row * 384 + (s << 5) + (lch << 3));
        }
        cpcommit();
    };

    issue(0); issue(1);

    for (int s = 0; s < 12; ++s) {
        if (s < 11) { cpwait<1>(); } else { cpwait<0>(); }
        __syncthreads();
        if (s + 2 < 12) issue(s + 2);

        const uint32_t Ab = sb + (uint32_t)(s % 3) * FC11_STG;
        const uint32_t Bb = Ab + 10240u;
#pragma unroll
        for (int ks = 0; ks < 2; ++ks) {
            const int kk = ks << 4;
            uint32_t a[4][4];
#pragma unroll
            for (int mt = 0; mt < 4; ++mt) {
                int row = wm * 64 + mt * 16 + (lane & 15);
                ldsm_x4(a[mt][0], a[mt][1], a[mt][2], a[mt][3],
                        Ab + row * APITCH + ((kk + ((lane >> 4) << 3)) << 1));
            }
#pragma unroll
            for (int np = 0; np < 2; ++np) {
                int n = wn * 32 + np * 16 + ((lane >> 4) << 3) + (lane & 7);
                uint32_t b0, b1, b2, b3;
                ldsm_x4(b0, b1, b2, b3, Bb + n * APITCH + ((kk + (lane & 8)) << 1));
#pragma unroll
                for (int mt = 0; mt < 4; ++mt) {
                    mma16816(acc[mt][2*np][0], acc[mt][2*np][1], acc[mt][2*np][2], acc[mt][2*np][3],
                             a[mt][0], a[mt][1], a[mt][2], a[mt][3], b0, b1);
                    mma16816(acc[mt][2*np+1][0], acc[mt][2*np+1][1], acc[mt][2*np+1][2], acc[mt][2*np+1][3],
                             a[mt][0], a[mt][1], a[mt][2], a[mt][3], b2, b3);
                }
            }
        }
    }

    // epilogue: fragments hold (even,odd) col pairs -> dnew directly
#pragma unroll
    for (int mt = 0; mt < 4; ++mt)
#pragma unroll
        for (int nn = 0; nn < 4; ++nn) {
            int n = wn * 32 + (nn >> 1) * 16 + (nn & 1) * 8 + 2 * t4;
            float be = b11s[n], bo = b11s[n + 1];
            int r0 = m0 + wm * 64 + mt * 16 + g;
#pragma unroll
            for (int hh = 0; hh < 2; ++hh) {
                float v0 = acc[mt][nn][2 * hh]     + be;
                float v1 = acc[mt][nn][2 * hh + 1] + bo;
                v0 = v0 > 0.f ? v0 : 0.01f * v0;
                v1 = v1 > 0.f ? v1 : 0.01f * v1;
                float jn = fmaxf(v0, 0.f);
                float delta = sqrtf(jn * jn + v1 * v1 + 1e-12f);
                float dn = __fdividef(0.1f * (delta - 0.01f),
                                      fmaxf(delta, 1e-12f) * 0.09f);
                dn = fminf(fmaxf(dn, 0.f), 1.f);
                g_dnew[(size_t)(r0 + 8 * hh) * 64 + (n >> 1)] = dn;
            }
        }
}

// ---------------------------------------------------------------------------
// Kernel B: prefix-max of dnew over T -> dmg bf16 hi/lo cols [128,192)
// ---------------------------------------------------------------------------
__global__ void k_prefixmax()
{
    int t = blockIdx.x * blockDim.x + threadIdx.x;   // 0..16383
    int b = t >> 6, p = t & 63;
    const float* src = g_dnew + (size_t)b * 512 * 64 + p;
    __nv_bfloat16* dh = g_Ah + (size_t)b * 512 * 192 + 128 + p;
    __nv_bfloat16* dl = g_Al + (size_t)b * 512 * 192 + 128 + p;
    float run = 0.f;
    for (int t0 = 0; t0 < 512; t0 += 8) {
        float v[8];
#pragma unroll
        for (int i = 0; i < 8; ++i) v[i] = src[(size_t)(t0 + i) * 64];
#pragma unroll
        for (int i = 0; i < 8; ++i) {
            run = fmaxf(run, v[i]);
            __nv_bfloat16 hi = __float2bfloat16(run);
            dh[(size_t)(t0 + i) * 192] = hi;
            dl[(size_t)(t0 + i) * 192] = __float2bfloat16(run - __bfloat162float(hi));
        }
    }
}

// ---------------------------------------------------------------------------
// Kernel C: fc12 mma.sync GEMM. grid (1024,2): BM=128, BN=192, K'=576.
//   8 warps as 2M x 4N -> warp tile 64x48, acc[4][6][4].
//   18 stages Kc=32, 3-stage cp.async (25600 B/stage, 76800 total).
//   Epilogue in two 32-row halves via warp-private smem slabs.
// ---------------------------------------------------------------------------
#define FC12_STG  25600
#define FC12_SMEM 76800

__global__ void __launch_bounds__(256, 1) k_fc12_mma()
{
    extern __shared__ char smem[];
    const uint32_t sb = smem_u32(smem);
    const int tid  = threadIdx.x;
    const int lane = tid & 31;
    const int w    = tid >> 5;
    const int wm   = w >> 2;            // 0..1
    const int wn   = w & 3;             // 0..3
    const int g    = lane >> 2;
    const int t4   = lane & 3;
    const int m0   = blockIdx.x << 7;
    const int gy   = blockIdx.y;        // 0..1 (cols gy*192..)

    float acc[4][6][4];
#pragma unroll
    for (int a = 0; a < 4; ++a)
#pragma unroll
        for (int b = 0; b < 6; ++b)
#pragma unroll
            for (int c = 0; c < 4; ++c) acc[a][b][c] = 0.f;

    const int lrow = tid >> 2, lch = tid & 3;

    auto issue = [&](int s) {
        const int seg = s / 6;                 // 0:hi 1:lo 2:hi
        const int kk0 = (s % 6) << 5;
        const __nv_bfloat16* Asrc = (seg == 1) ? g_Al : g_Ah;
        uint32_t base = sb + (uint32_t)(s % 3) * FC12_STG;
#pragma unroll
        for (int i = 0; i < 2; ++i) {
            int row = lrow + (i << 6);
            cpasync16(base + row * APITCH + (lch << 4),
                      Asrc + (size_t)(m0 + row) * 192 + kk0 + (lch << 3));
        }
#pragma unroll
        for (int i = 0; i < 3; ++i) {
            int row = lrow + (i << 6);
            cpasync16(base + 10240 + row * APITCH + (lch << 4),
                      g_Bp + (size_t)(gy * 192 + row) * 576 + (s << 5) + (lch << 3));
        }
        cpcommit();
    };

    issue(0); issue(1);

    for (int s = 0; s < 18; ++s) {
        if (s < 17) { cpwait<1>(); } else { cpwait<0>(); }
        __syncthreads();
        if (s + 2 < 18) issue(s + 2);

        const uint32_t Ab = sb + (uint32_t)(s % 3) * FC12_STG;
        const uint32_t Bb = Ab + 10240u;
#pragma unroll
        for (int ks = 0; ks < 2; ++ks) {
            const int kk = ks << 4;
            uint32_t a[4][4];
#pragma unroll
            for (int mt = 0; mt < 4; ++mt) {
                int row = wm * 64 + mt * 16 + (lane & 15);
                ldsm_x4(a[mt][0], a[mt][1], a[mt][2], a[mt][3],
                        Ab + row * APITCH + ((kk + ((lane >> 4) << 3)) << 1));
            }
#pragma unroll
            for (int np = 0; np < 3; ++np) {
                int n = wn * 48 + np * 16 + ((lane >> 4) << 3) + (lane & 7);
                uint32_t b0, b1, b2, b3;
                ldsm_x4(b0, b1, b2, b3, Bb + n * APITCH + ((kk + (lane & 8)) << 1));
#pragma unroll
                for (int mt = 0; mt < 4; ++mt) {
                    mma16816(acc[mt][2*np][0], acc[mt][2*np][1], acc[mt][2*np][2], acc[mt][2*np][3],
                             a[mt][0], a[mt][1], a[mt][2], a[mt][3], b0, b1);
                    mma16816(acc[mt][2*np+1][0], acc[mt][2*np+1][1], acc[mt][2*np+1][2], acc[mt][2*np+1][3],
                             a[mt][0], a[mt][1], a[mt][2], a[mt][3], b2, b3);
                }
            }
        }
    }

    // ---------------- epilogue: two 32-row halves via warp slabs ----------------
    __syncthreads();
    float* slab = (float*)smem + w * 1664;     // 32 x 52 floats per warp
    const int cb  = gy * 192 + wn * 48;
    const int pbi = gy * 64 + wn * 16;

#pragma unroll
    for (int mh = 0; mh < 2; ++mh) {
#pragma unroll
        for (int mt2 = 0; mt2 < 2; ++mt2) {
            int mt = mh * 2 + mt2;
#pragma unroll
            for (int nn = 0; nn < 6; ++nn) {
                int row = mt2 * 16 + g;
                int col = nn * 8 + 2 * t4;
                slab[row * 52 + col]           = acc[mt][nn][0];
                slab[row * 52 + col + 1]       = acc[mt][nn][1];
                slab[(row + 8) * 52 + col]     = acc[mt][nn][2];
                slab[(row + 8) * 52 + col + 1] = acc[mt][nn][3];
            }
        }
        __syncwarp();

        const int mbase = m0 + wm * 64 + mh * 32;
#pragma unroll 1
        for (int r = 0; r < 32; ++r) {
            if (lane < 16) {
                float s0 = slab[r * 52 + 3 * lane];
                float s1 = slab[r * 52 + 3 * lane + 1];
                float s2 = slab[r * 52 + 3 * lane + 2];
                float seq = sqrtf(s0 * s0 - s0 * s1 + s1 * s1 + 3.f * s2 * s2 + 1e-12f);
                g_seq[(size_t)(mbase + r) * 128 + pbi + lane] = seq;
            }
            if (lane < 12) {
                float4 v = *(float4*)&slab[r * 52 + 4 * lane];
                *(float4*)&g_strain[(size_t)(mbase + r) * 384 + cb + 4 * lane] = v;
            }
        }
        __syncwarp();
    }
}

// ---------------------------------------------------------------------------
// Kernel E: J2 radial-return ep chains
// ---------------------------------------------------------------------------
__global__ void k_ep()
{
    int t = blockIdx.x * 256 + threadIdx.x;
    int b = t >> 7, p = t & 127;
    const float* sq = g_seq   + (size_t)b * 512 * 128 + p;
    float*       sc = g_scale + (size_t)b * 512 * 128 + p;
    const float SY = 10.f, H = 100.f;
    const float INV = (float)(1.0 / (3.0 * (1000.0 / 2.6) + 100.0));
    float ep = 0.f;
    for (int t0 = 0; t0 < 512; t0 += 8) {
        float v[8];
#pragma unroll
        for (int i = 0; i < 8; ++i) v[i] = sq[(size_t)(t0 + i) * 128];
        float out[8];
#pragma unroll
        for (int i = 0; i < 8; ++i) {
            float fy = v[i] - fmaf(H, ep, SY);
            if (fy > 0.f) {
                ep = fmaf(fy, INV, ep);
                out[i] = __fdividef(fmaf(H, ep, SY), v[i]);
            } else {
                out[i] = 1.f;
            }
        }
#pragma unroll
        for (int i = 0; i < 8; ++i) sc[(size_t)(t0 + i) * 128] = out[i];
    }
}

// ---------------------------------------------------------------------------
// Kernel F: fc2 + softplus
// ---------------------------------------------------------------------------
__global__ void k_fc2(const float* __restrict__ W2, float* __restrict__ out)
{
    __shared__ float w2s[6 * 384];
    int tid = threadIdx.x;
    for (int i = tid; i < 2304; i += 256) w2s[i] = W2[i];
    __syncthreads();

    int warp = tid >> 5, lane = tid & 31;
    int m = blockIdx.x * 8 + warp;
    const float* sig = g_strain + (size_t)m * 384;
    const float* scl = g_scale  + (size_t)m * 128;
    float acc[6] = {0.f, 0.f, 0.f, 0.f, 0.f, 0.f};
#pragma unroll
    for (int q = 0; q < 4; ++q) {
        int p = lane + 32 * q;
        float s = scl[p];
        float f0 = sig[3 * p], f1 = sig[3 * p + 1], f2 = sig[3 * p + 2];
        float g0 = s * f0, g1 = s * f1, g2 = s * f2;
#pragma unroll
        for (int o = 0; o < 6; ++o) {
            acc[o] = fmaf(g0, w2s[o * 384 + 3 * p],     acc[o]);
            acc[o] = fmaf(g1, w2s[o * 384 + 3 * p + 1], acc[o]);
            acc[o] = fmaf(g2, w2s[o * 384 + 3 * p + 2], acc[o]);
        }
    }
#pragma unroll
    for (int o = 0; o < 6; ++o)
#pragma unroll
        for (int off = 16; off; off >>= 1)
            acc[o] += __shfl_xor_sync(0xffffffffu, acc[o], off);
    if (lane == 0) {
#pragma unroll
        for (int o = 0; o < 6; ++o) {
            float v = acc[o];
            float sp = fmaxf(v, 0.f) + log1pf(expf(-fabsf(v)));
            out[(size_t)m * 6 + o] = sp;
        }
    }
}

// ---------------------------------------------------------------------------
extern "C" void kernel_launch(void* const* d_in, const int* in_sizes, int n_in,
                              void* d_out, int out_size)
{
    const float* x   = (const float*)d_in[0];
    const float* W11 = (const float*)d_in[1];
    const float* b11 = (const float*)d_in[2];
    const float* W12 = (const float*)d_in[3];
    const float* W2  = (const float*)d_in[4];
    float* out = (float*)d_out;

    (void)in_sizes; (void)n_in; (void)out_size;

    cudaFuncSetAttribute(k_fc11_mma, cudaFuncAttributeMaxDynamicSharedMemorySize, FC11_SMEM);
    cudaFuncSetAttribute(k_fc12_mma, cudaFuncAttributeMaxDynamicSharedMemorySize, FC12_SMEM);

    k_splitx<<<MM / 8, 256>>>(x);
    k_prepB11<<<64, 256>>>(W11);
    k_prepB<<<288, 256>>>(W12);
    k_fc11_mma<<<MM / 128, 256, FC11_SMEM>>>(b11);
    k_prefixmax<<<64, 256>>>();
    k_fc12_mma<<<dim3(MM / 128, 2), 256, FC12_SMEM>>>();
    k_ep<<<128, 256>>>();
    k_fc2<<<MM / 8, 256>>>(W2, out);
}

// round 9
// speedup vs baseline: 1.6367x; 1.1871x over previous
#include <cuda_runtime.h>
#include <cuda_bf16.h>
#include <cstdint>

// ---------------------------------------------------------------------------
// Pipeline:
//   S : split x -> bf16 hi/lo            -> g_Ah/g_Al [M,192] cols 0..127
//   P1: split W11 (hi|hi|lo)             -> g_B11 [128,384] bf16
//   P2: fold plane-stress D into W12, split -> g_Bp [384,576] bf16
//   A : fc11 mma.sync GEMM + dnew        -> g_dnew  [M,64]
//   B : prefix-max over T -> dmg hi/lo   -> g_Ah/g_Al cols 128..191
//   C : fc12 mma.sync GEMM               -> g_strain (= sig_tr) [M,384]
//   T : fused seq + J2 scan + fc2 + softplus -> out  (one CTA per batch)
// R9: GEMM rate is pinned at ~105 TMAC/s (legacy mma.sync ceiling on sm_103);
// recover non-GEMM time: fused tail kernel, lighter fc12 epilogue.
// ---------------------------------------------------------------------------

typedef unsigned long long u64;

#define MM 131072   // 256*512

__device__ __align__(16) float g_dnew[(size_t)MM * 64];
__device__ __align__(16) float g_strain[(size_t)MM * 384];
__device__ __align__(16) __nv_bfloat16 g_Ah[(size_t)MM * 192];
__device__ __align__(16) __nv_bfloat16 g_Al[(size_t)MM * 192];
__device__ __align__(16) __nv_bfloat16 g_Bp[384 * 576];
__device__ __align__(16) __nv_bfloat16 g_B11[128 * 384];

__device__ __forceinline__ uint32_t smem_u32(const void* p) {
    uint32_t a;
    asm("{ .reg .u64 t; cvta.to.shared.u64 t, %1; cvt.u32.u64 %0, t; }" : "=r"(a) : "l"(p));
    return a;
}
__device__ __forceinline__ void cpasync16(uint32_t dst, const void* src) {
    asm volatile("cp.async.ca.shared.global [%0], [%1], 16;" :: "r"(dst), "l"(src) : "memory");
}
__device__ __forceinline__ void cpcommit() {
    asm volatile("cp.async.commit_group;" ::: "memory");
}
template <int N>
__device__ __forceinline__ void cpwait() {
    asm volatile("cp.async.wait_group %0;" :: "n"(N) : "memory");
}
__device__ __forceinline__ void ldsm_x4(uint32_t& r0, uint32_t& r1, uint32_t& r2,
                                        uint32_t& r3, uint32_t addr) {
    asm volatile("ldmatrix.sync.aligned.m8n8.x4.shared.b16 {%0,%1,%2,%3}, [%4];"
                 : "=r"(r0), "=r"(r1), "=r"(r2), "=r"(r3) : "r"(addr));
}
__device__ __forceinline__ void mma16816(float& c0, float& c1, float& c2, float& c3,
                                         uint32_t a0, uint32_t a1, uint32_t a2, uint32_t a3,
                                         uint32_t b0, uint32_t b1) {
    asm volatile("mma.sync.aligned.m16n8k16.row.col.f32.bf16.bf16.f32 "
                 "{%0,%1,%2,%3}, {%4,%5,%6,%7}, {%8,%9}, {%0,%1,%2,%3};"
                 : "+f"(c0), "+f"(c1), "+f"(c2), "+f"(c3)
                 : "r"(a0), "r"(a1), "r"(a2), "r"(a3), "r"(b0), "r"(b1));
}

#define APITCH 80   // smem row pitch: 64B data + 16B pad (conflict-free ldsm)

// ---------------------------------------------------------------------------
// Kernel S: split x into bf16 hi/lo -> g_Ah/g_Al cols [0,128)
// ---------------------------------------------------------------------------
__global__ void k_splitx(const float* __restrict__ x)
{
    int idx = blockIdx.x * 256 + threadIdx.x;     // 0 .. MM*32-1
    int m = idx >> 5, q = (idx & 31) << 2;
    float4 v = *(const float4*)(x + (size_t)m * 128 + q);
    __nv_bfloat16 h[4], l[4];
    float f[4] = {v.x, v.y, v.z, v.w};
#pragma unroll
    for (int i = 0; i < 4; ++i) {
        h[i] = __float2bfloat16(f[i]);
        l[i] = __float2bfloat16(f[i] - __bfloat162float(h[i]));
    }
    *(u64*)(g_Ah + (size_t)m * 192 + q) = *(u64*)h;
    *(u64*)(g_Al + (size_t)m * 192 + q) = *(u64*)l;
}

// ---------------------------------------------------------------------------
// Kernel P1: split W11 -> g_B11 [128,384]: [0,128)=hi, [128,256)=hi, [256,384)=lo
// ---------------------------------------------------------------------------
__global__ void k_prepB11(const float* __restrict__ W11)
{
    int t = blockIdx.x * 256 + threadIdx.x;
    if (t >= 128 * 128) return;
    int n = t >> 7, k = t & 127;
    float w = W11[(size_t)n * 128 + k];
    __nv_bfloat16 hi = __float2bfloat16(w);
    float lo = w - __bfloat162float(hi);
    g_B11[(size_t)n * 384 + k]       = hi;
    g_B11[(size_t)n * 384 + 128 + k] = hi;
    g_B11[(size_t)n * 384 + 256 + k] = __float2bfloat16(lo);
}

// ---------------------------------------------------------------------------
// Kernel P2: fold plane-stress D into W12, split -> g_Bp [384,576]
// ---------------------------------------------------------------------------
__global__ void k_prepB(const float* __restrict__ W12)
{
    int t = blockIdx.x * 256 + threadIdx.x;
    if (t >= 384 * 192) return;
    int n = t / 192, k = t % 192;
    int p3 = (n / 3) * 3, j = n % 3;
    const float C   = 1098.9010989010989f;   // E/(1-nu^2)
    const float CNU = 329.67032967032966f;   // C*nu
    const float CSH = 384.61538461538464f;   // C*(1-nu)/2
    float w;
    if (j == 0)      w = C   * W12[(size_t)p3 * 192 + k] + CNU * W12[(size_t)(p3 + 1) * 192 + k];
    else if (j == 1) w = CNU * W12[(size_t)p3 * 192 + k] + C   * W12[(size_t)(p3 + 1) * 192 + k];
    else             w = CSH * W12[(size_t)n * 192 + k];
    __nv_bfloat16 hi = __float2bfloat16(w);
    float lo = w - __bfloat162float(hi);
    g_Bp[(size_t)n * 576 + k]       = hi;
    g_Bp[(size_t)n * 576 + 192 + k] = hi;
    g_Bp[(size_t)n * 576 + 384 + k] = __float2bfloat16(lo);
}

// ---------------------------------------------------------------------------
// Kernel A: fc11 mma.sync GEMM (R8 config: best measured 60us).
//   grid (1024): BM=128, BN=128, K'=384. 8 warps 2Mx4N -> warp tile 64x32.
//   12 stages Kc=32, 3-stage cp.async.
// ---------------------------------------------------------------------------
#define FC11_STG  20480
#define FC11_SMEM 61440

__global__ void __launch_bounds__(256, 1) k_fc11_mma(const float* __restrict__ b11)
{
    extern __shared__ char smem[];
    const uint32_t sb = smem_u32(smem);
    const int tid  = threadIdx.x;
    const int lane = tid & 31;
    const int w    = tid >> 5;
    const int wm   = w >> 2;            // 0..1
    const int wn   = w & 3;             // 0..3
    const int g    = lane >> 2;
    const int t4   = lane & 3;
    const int m0   = blockIdx.x << 7;

    __shared__ float b11s[128];
    if (tid < 128) b11s[tid] = b11[tid];

    float acc[4][4][4];
#pragma unroll
    for (int a = 0; a < 4; ++a)
#pragma unroll
        for (int b = 0; b < 4; ++b)
#pragma unroll
            for (int c = 0; c < 4; ++c) acc[a][b][c] = 0.f;

    const int lrow = tid >> 2, lch = tid & 3;

    auto issue = [&](int s) {
        const int seg = s >> 2;                 // 0:hi 1:lo 2:hi
        const int kk0 = (s & 3) << 5;
        const __nv_bfloat16* Asrc = (seg == 1) ? g_Al : g_Ah;
        uint32_t base = sb + (uint32_t)(s % 3) * FC11_STG;
#pragma unroll
        for (int i = 0; i < 2; ++i) {
            int row = lrow + (i << 6);
            cpasync16(base + row * APITCH + (lch << 4),
                      Asrc + (size_t)(m0 + row) * 192 + kk0 + (lch << 3));
        }
#pragma unroll
        for (int i = 0; i < 2; ++i) {
            int row = lrow + (i << 6);
            cpasync16(base + 10240 + row * APITCH + (lch << 4),
                      g_B11 + (size_t)row * 384 + (s << 5) + (lch << 3));
        }
        cpcommit();
    };

    issue(0); issue(1);

    for (int s = 0; s < 12; ++s) {
        if (s < 11) { cpwait<1>(); } else { cpwait<0>(); }
        __syncthreads();
        if (s + 2 < 12) issue(s + 2);

        const uint32_t Ab = sb + (uint32_t)(s % 3) * FC11_STG;
        const uint32_t Bb = Ab + 10240u;
#pragma unroll
        for (int ks = 0; ks < 2; ++ks) {
            const int kk = ks << 4;
            uint32_t a[4][4];
#pragma unroll
            for (int mt = 0; mt < 4; ++mt) {
                int row = wm * 64 + mt * 16 + (lane & 15);
                ldsm_x4(a[mt][0], a[mt][1], a[mt][2], a[mt][3],
                        Ab + row * APITCH + ((kk + ((lane >> 4) << 3)) << 1));
            }
#pragma unroll
            for (int np = 0; np < 2; ++np) {
                int n = wn * 32 + np * 16 + ((lane >> 4) << 3) + (lane & 7);
                uint32_t b0, b1, b2, b3;
                ldsm_x4(b0, b1, b2, b3, Bb + n * APITCH + ((kk + (lane & 8)) << 1));
#pragma unroll
                for (int mt = 0; mt < 4; ++mt) {
                    mma16816(acc[mt][2*np][0], acc[mt][2*np][1], acc[mt][2*np][2], acc[mt][2*np][3],
                             a[mt][0], a[mt][1], a[mt][2], a[mt][3], b0, b1);
                    mma16816(acc[mt][2*np+1][0], acc[mt][2*np+1][1], acc[mt][2*np+1][2], acc[mt][2*np+1][3],
                             a[mt][0], a[mt][1], a[mt][2], a[mt][3], b2, b3);
                }
            }
        }
    }

    // epilogue: fragments hold (even,odd) col pairs -> dnew directly
#pragma unroll
    for (int mt = 0; mt < 4; ++mt)
#pragma unroll
        for (int nn = 0; nn < 4; ++nn) {
            int n = wn * 32 + (nn >> 1) * 16 + (nn & 1) * 8 + 2 * t4;
            float be = b11s[n], bo = b11s[n + 1];
            int r0 = m0 + wm * 64 + mt * 16 + g;
#pragma unroll
            for (int hh = 0; hh < 2; ++hh) {
                float v0 = acc[mt][nn][2 * hh]     + be;
                float v1 = acc[mt][nn][2 * hh + 1] + bo;
                v0 = v0 > 0.f ? v0 : 0.01f * v0;
                v1 = v1 > 0.f ? v1 : 0.01f * v1;
                float jn = fmaxf(v0, 0.f);
                float delta = sqrtf(jn * jn + v1 * v1 + 1e-12f);
                float dn = __fdividef(0.1f * (delta - 0.01f),
                                      fmaxf(delta, 1e-12f) * 0.09f);
                dn = fminf(fmaxf(dn, 0.f), 1.f);
                g_dnew[(size_t)(r0 + 8 * hh) * 64 + (n >> 1)] = dn;
            }
        }
}

// ---------------------------------------------------------------------------
// Kernel B: prefix-max of dnew over T -> dmg bf16 hi/lo cols [128,192)
// ---------------------------------------------------------------------------
__global__ void k_prefixmax()
{
    int t = blockIdx.x * blockDim.x + threadIdx.x;   // 0..16383
    int b = t >> 6, p = t & 63;
    const float* src = g_dnew + (size_t)b * 512 * 64 + p;
    __nv_bfloat16* dh = g_Ah + (size_t)b * 512 * 192 + 128 + p;
    __nv_bfloat16* dl = g_Al + (size_t)b * 512 * 192 + 128 + p;
    float run = 0.f;
    for (int t0 = 0; t0 < 512; t0 += 8) {
        float v[8];
#pragma unroll
        for (int i = 0; i < 8; ++i) v[i] = src[(size_t)(t0 + i) * 64];
#pragma unroll
        for (int i = 0; i < 8; ++i) {
            run = fmaxf(run, v[i]);
            __nv_bfloat16 hi = __float2bfloat16(run);
            dh[(size_t)(t0 + i) * 192] = hi;
            dl[(size_t)(t0 + i) * 192] = __float2bfloat16(run - __bfloat162float(hi));
        }
    }
}

// ---------------------------------------------------------------------------
// Kernel C: fc12 mma.sync GEMM (R5 config + tail-wait fix + direct stores).
//   grid (1024,4): BM=128, BN=96, K'=576 (18 stages Kc=32), 3-stage cp.async,
//   256 thr, warp grid 4Mx2N: warp tile 32x48, 2 CTA/SM.
// ---------------------------------------------------------------------------
#define FC12_STG  17920
#define FC12_SMEM 53760

__global__ void __launch_bounds__(256, 2) k_fc12_mma()
{
    extern __shared__ char smem[];
    const uint32_t sb = smem_u32(smem);
    const int tid  = threadIdx.x;
    const int lane = tid & 31;
    const int w    = tid >> 5;
    const int wm   = w >> 1;
    const int wn   = w & 1;
    const int g    = lane >> 2;
    const int t4   = lane & 3;
    const int m0   = blockIdx.x << 7;
    const int gy   = blockIdx.y;          // n-tile: cols gy*96..

    float acc[2][6][4];
#pragma unroll
    for (int a = 0; a < 2; ++a)
#pragma unroll
        for (int b = 0; b < 6; ++b)
#pragma unroll
            for (int c = 0; c < 4; ++c) acc[a][b][c] = 0.f;

    const int lrow = tid >> 2, lch = tid & 3;

    auto issue = [&](int s) {
        const int seg = s / 6;                 // 0:hi 1:lo 2:hi
        const int kk0 = (s % 6) << 5;
        const __nv_bfloat16* Asrc = (seg == 1) ? g_Al : g_Ah;
        uint32_t base = sb + (uint32_t)(s % 3) * FC12_STG;
#pragma unroll
        for (int i = 0; i < 2; ++i) {
            int row = lrow + (i << 6);
            cpasync16(base + row * APITCH + (lch << 4),
                      Asrc + (size_t)(m0 + row) * 192 + kk0 + (lch << 3));
        }
#pragma unroll
        for (int i = 0; i < 2; ++i) {
            int id = tid + (i << 8);
            if (id < 384) {
                int row = id >> 2, c = id & 3;
                cpasync16(base + 10240 + row * APITCH + (c << 4),
                          g_Bp + (size_t)(gy * 96 + row) * 576 + (s << 5) + (c << 3));
            }
        }
        cpcommit();
    };

    issue(0); issue(1);

    for (int s = 0; s < 18; ++s) {
        if (s < 17) { cpwait<1>(); } else { cpwait<0>(); }
        __syncthreads();
        if (s + 2 < 18) issue(s + 2);

        const uint32_t Ab = sb + (uint32_t)(s % 3) * FC12_STG;
        const uint32_t Bb = Ab + 10240u;
#pragma unroll
        for (int ks = 0; ks < 2; ++ks) {
            const int kk = ks << 4;
            uint32_t a[2][4];
#pragma unroll
            for (int mt = 0; mt < 2; ++mt) {
                int row = wm * 32 + mt * 16 + (lane & 15);
                ldsm_x4(a[mt][0], a[mt][1], a[mt][2], a[mt][3],
                        Ab + row * APITCH + ((kk + ((lane >> 4) << 3)) << 1));
            }
#pragma unroll
            for (int np = 0; np < 3; ++np) {
                int n = wn * 48 + np * 16 + ((lane >> 4) << 3) + (lane & 7);
                uint32_t b0, b1, b2, b3;
                ldsm_x4(b0, b1, b2, b3, Bb + n * APITCH + ((kk + (lane & 8)) << 1));
#pragma unroll
                for (int mt = 0; mt < 2; ++mt) {
                    mma16816(acc[mt][2*np][0], acc[mt][2*np][1], acc[mt][2*np][2], acc[mt][2*np][3],
                             a[mt][0], a[mt][1], a[mt][2], a[mt][3], b0, b1);
                    mma16816(acc[mt][2*np+1][0], acc[mt][2*np+1][1], acc[mt][2*np+1][2], acc[mt][2*np+1][3],
                             a[mt][0], a[mt][1], a[mt][2], a[mt][3], b2, b3);
                }
            }
        }
    }

    // direct fragment stores (no slab, no seq)
    const int cb = gy * 96 + wn * 48;
#pragma unroll
    for (int mt = 0; mt < 2; ++mt) {
        int row0 = m0 + wm * 32 + mt * 16 + g;
#pragma unroll
        for (int j = 0; j < 6; ++j) {
            int col = cb + (j >> 1) * 16 + (j & 1) * 8 + 2 * t4;
            float2 vlo = make_float2(acc[mt][j][0], acc[mt][j][1]);
            float2 vhi = make_float2(acc[mt][j][2], acc[mt][j][3]);
            *(float2*)&g_strain[(size_t)row0 * 384 + col]       = vlo;
            *(float2*)&g_strain[(size_t)(row0 + 8) * 384 + col] = vhi;
        }
    }
}

// ---------------------------------------------------------------------------
// Kernel T: fused tail. One CTA per batch b (256 CTAs, 128 threads).
//   Per 32-t chunk: (1) cooperative load sig[32,384] -> smem,
//   (2) per-point seq + J2 radial-return chain + scale, in place,
//   (3) [32,384]x[384,6] GEMV + softplus -> out.
// ---------------------------------------------------------------------------
#define TAIL_SMEM (12288 + 49664)   // w2t [384][8] f32 + gs [32][388] f32

__global__ void __launch_bounds__(128, 3) k_tail(const float* __restrict__ W2,
                                                 float* __restrict__ out)
{
    extern __shared__ float ts[];
    float* w2t = ts;            // [384][8]
    float* gs  = ts + 3072;     // [32][388]
    const int tid = threadIdx.x;
    const int b   = blockIdx.x;

    for (int i = tid; i < 2304; i += 128) {
        int o = i / 384, k = i - o * 384;
        w2t[k * 8 + o] = W2[i];
    }

    const float SY = 10.f, H = 100.f;
    const float INV = (float)(1.0 / (3.0 * (1000.0 / 2.6) + 100.0));
    float ep = 0.f;
    const float* sigb = g_strain + (size_t)b * 512 * 384;
    const int tlb = tid >> 2, q = tid & 3;
    const int p = tid;

    for (int chunk = 0; chunk < 16; ++chunk) {
        __syncthreads();   // gs free (previous chunk's GEMV done; 1st iter: w2t ready)
        // (1) cooperative load: 32 rows x 384 f32
        const float* src = sigb + (size_t)chunk * 32 * 384;
        for (int i = tid; i < 32 * 96; i += 128) {
            int tl = i / 96, c4 = i - tl * 96;
            *(float4*)&gs[tl * 388 + (c4 << 2)] = *(const float4*)(src + tl * 384 + (c4 << 2));
        }
        __syncthreads();
        // (2) seq + plasticity chain for this thread's point p, in place
#pragma unroll 4
        for (int tl = 0; tl < 32; ++tl) {
            float* row = gs + tl * 388 + 3 * p;
            float s0 = row[0], s1 = row[1], s2 = row[2];
            float seq = sqrtf(s0 * s0 - s0 * s1 + s1 * s1 + 3.f * s2 * s2 + 1e-12f);
            float fy = seq - fmaf(H, ep, SY);
            float sc;
            if (fy > 0.f) {
                ep = fmaf(fy, INV, ep);
                sc = __fdividef(fmaf(H, ep, SY), seq);
            } else {
                sc = 1.f;
            }
            row[0] = sc * s0; row[1] = sc * s1; row[2] = sc * s2;
        }
        __syncthreads();
        // (3) GEMV: thread (tlb, q) accumulates k = 4i+q for t-row tlb
        float acc[6] = {0.f, 0.f, 0.f, 0.f, 0.f, 0.f};
        const float* grow = gs + tlb * 388;
#pragma unroll 8
        for (int i = 0; i < 96; ++i) {
            int k = (i << 2) + q;
            float gv = grow[k];
            float4 wa = *(float4*)&w2t[k * 8];
            float2 wb = *(float2*)&w2t[k * 8 + 4];
            acc[0] = fmaf(gv, wa.x, acc[0]);
            acc[1] = fmaf(gv, wa.y, acc[1]);
            acc[2] = fmaf(gv, wa.z, acc[2]);
            acc[3] = fmaf(gv, wa.w, acc[3]);
            acc[4] = fmaf(gv, wb.x, acc[4]);
            acc[5] = fmaf(gv, wb.y, acc[5]);
        }
#pragma unroll
        for (int o = 0; o < 6; ++o) {
            acc[o] += __shfl_xor_sync(0xffffffffu, acc[o], 1);
            acc[o] += __shfl_xor_sync(0xffffffffu, acc[o], 2);
        }
        if (q == 0) {
            int t = chunk * 32 + tlb;
            float* op = out + ((size_t)b * 512 + t) * 6;
#pragma unroll
            for (int o = 0; o < 6; ++o) {
                float v = acc[o];
                op[o] = fmaxf(v, 0.f) + log1pf(expf(-fabsf(v)));
            }
        }
    }
}

// ---------------------------------------------------------------------------
extern "C" void kernel_launch(void* const* d_in, const int* in_sizes, int n_in,
                              void* d_out, int out_size)
{
    const float* x   = (const float*)d_in[0];
    const float* W11 = (const float*)d_in[1];
    const float* b11 = (const float*)d_in[2];
    const float* W12 = (const float*)d_in[3];
    const float* W2  = (const float*)d_in[4];
    float* out = (float*)d_out;

    (void)in_sizes; (void)n_in; (void)out_size;

    cudaFuncSetAttribute(k_fc11_mma, cudaFuncAttributeMaxDynamicSharedMemorySize, FC11_SMEM);
    cudaFuncSetAttribute(k_fc12_mma, cudaFuncAttributeMaxDynamicSharedMemorySize, FC12_SMEM);
    cudaFuncSetAttribute(k_tail,     cudaFuncAttributeMaxDynamicSharedMemorySize, TAIL_SMEM);

    k_splitx<<<MM / 8, 256>>>(x);
    k_prepB11<<<64, 256>>>(W11);
    k_prepB<<<288, 256>>>(W12);
    k_fc11_mma<<<MM / 128, 256, FC11_SMEM>>>(b11);
    k_prefixmax<<<64, 256>>>();
    k_fc12_mma<<<dim3(MM / 128, 4), 256, FC12_SMEM>>>();
    k_tail<<<256, 128, TAIL_SMEM>>>(W2, out);
}

// round 10
// speedup vs baseline: 1.8574x; 1.1348x over previous
#include <cuda_runtime.h>
#include <cuda_fp16.h>
#include <cstdint>

// ---------------------------------------------------------------------------
// Pipeline (fp16 2-term split: C ~= a1*w1 + a2*w1, w-residual dropped):
//   S : split x -> fp16 a1/a2            -> g_Ah/g_Al [M,192] cols 0..127
//   P1: W11 -> fp16 hi                   -> g_B11 [128,128]
//   P2: fold plane-stress D into W12 -> fp16 hi -> g_Bp [384,192]
//   A : fc11 mma.sync GEMM (K'=256) + dnew -> g_dnew [M,64]
//   B : prefix-max over T -> dmg a1/a2   -> g_Ah/g_Al cols 128..191
//   C : fc12 mma.sync GEMM (K'=384)      -> g_strain (= sig_tr) [M,384]
//   T : fused seq + J2 scan + fc2 + softplus -> out
// R10: GEMM MACs cut 33% by fp16 2-term split (error ~3e-4 << 1e-3 gate).
// ---------------------------------------------------------------------------

typedef unsigned long long u64;

#define MM 131072   // 256*512

__device__ __align__(16) float g_dnew[(size_t)MM * 64];
__device__ __align__(16) float g_strain[(size_t)MM * 384];
__device__ __align__(16) __half g_Ah[(size_t)MM * 192];
__device__ __align__(16) __half g_Al[(size_t)MM * 192];
__device__ __align__(16) __half g_Bp[384 * 192];
__device__ __align__(16) __half g_B11[128 * 128];

__device__ __forceinline__ uint32_t smem_u32(const void* p) {
    uint32_t a;
    asm("{ .reg .u64 t; cvta.to.shared.u64 t, %1; cvt.u32.u64 %0, t; }" : "=r"(a) : "l"(p));
    return a;
}
__device__ __forceinline__ void cpasync16(uint32_t dst, const void* src) {
    asm volatile("cp.async.ca.shared.global [%0], [%1], 16;" :: "r"(dst), "l"(src) : "memory");
}
__device__ __forceinline__ void cpcommit() {
    asm volatile("cp.async.commit_group;" ::: "memory");
}
template <int N>
__device__ __forceinline__ void cpwait() {
    asm volatile("cp.async.wait_group %0;" :: "n"(N) : "memory");
}
__device__ __forceinline__ void ldsm_x4(uint32_t& r0, uint32_t& r1, uint32_t& r2,
                                        uint32_t& r3, uint32_t addr) {
    asm volatile("ldmatrix.sync.aligned.m8n8.x4.shared.b16 {%0,%1,%2,%3}, [%4];"
                 : "=r"(r0), "=r"(r1), "=r"(r2), "=r"(r3) : "r"(addr));
}
__device__ __forceinline__ void mma16816(float& c0, float& c1, float& c2, float& c3,
                                         uint32_t a0, uint32_t a1, uint32_t a2, uint32_t a3,
                                         uint32_t b0, uint32_t b1) {
    asm volatile("mma.sync.aligned.m16n8k16.row.col.f32.f16.f16.f32 "
                 "{%0,%1,%2,%3}, {%4,%5,%6,%7}, {%8,%9}, {%0,%1,%2,%3};"
                 : "+f"(c0), "+f"(c1), "+f"(c2), "+f"(c3)
                 : "r"(a0), "r"(a1), "r"(a2), "r"(a3), "r"(b0), "r"(b1));
}

#define APITCH 80   // smem row pitch: 64B data + 16B pad (conflict-free ldsm)

// ---------------------------------------------------------------------------
// Kernel S: split x into fp16 a1/a2 -> g_Ah/g_Al cols [0,128)
// ---------------------------------------------------------------------------
__global__ void k_splitx(const float* __restrict__ x)
{
    int idx = blockIdx.x * 256 + threadIdx.x;     // 0 .. MM*32-1
    int m = idx >> 5, q = (idx & 31) << 2;
    float4 v = *(const float4*)(x + (size_t)m * 128 + q);
    __half h[4], l[4];
    float f[4] = {v.x, v.y, v.z, v.w};
#pragma unroll
    for (int i = 0; i < 4; ++i) {
        h[i] = __float2half(f[i]);
        l[i] = __float2half(f[i] - __half2float(h[i]));
    }
    *(u64*)(g_Ah + (size_t)m * 192 + q) = *(u64*)h;
    *(u64*)(g_Al + (size_t)m * 192 + q) = *(u64*)l;
}

// ---------------------------------------------------------------------------
// Kernel P1: W11 -> fp16 -> g_B11 [128,128]
// ---------------------------------------------------------------------------
__global__ void k_prepB11(const float* __restrict__ W11)
{
    int t = blockIdx.x * 256 + threadIdx.x;
    if (t >= 128 * 128) return;
    g_B11[t] = __float2half(W11[t]);
}

// ---------------------------------------------------------------------------
// Kernel P2: fold plane-stress D into W12 -> fp16 -> g_Bp [384,192]
// ---------------------------------------------------------------------------
__global__ void k_prepB(const float* __restrict__ W12)
{
    int t = blockIdx.x * 256 + threadIdx.x;
    if (t >= 384 * 192) return;
    int n = t / 192, k = t % 192;
    int p3 = (n / 3) * 3, j = n % 3;
    const float C   = 1098.9010989010989f;   // E/(1-nu^2)
    const float CNU = 329.67032967032966f;   // C*nu
    const float CSH = 384.61538461538464f;   // C*(1-nu)/2
    float w;
    if (j == 0)      w = C   * W12[(size_t)p3 * 192 + k] + CNU * W12[(size_t)(p3 + 1) * 192 + k];
    else if (j == 1) w = CNU * W12[(size_t)p3 * 192 + k] + C   * W12[(size_t)(p3 + 1) * 192 + k];
    else             w = CSH * W12[(size_t)n * 192 + k];
    g_Bp[(size_t)n * 192 + k] = __float2half(w);
}

// ---------------------------------------------------------------------------
// Kernel A: fc11 mma.sync GEMM. grid (1024): BM=128, BN=128, K'=256 (8 stages).
//   8 warps 2Mx4N -> warp tile 64x32. 3-stage cp.async.
// ---------------------------------------------------------------------------
#define FC11_STG  20480
#define FC11_SMEM 61440

__global__ void __launch_bounds__(256, 1) k_fc11_mma(const float* __restrict__ b11)
{
    extern __shared__ char smem[];
    const uint32_t sb = smem_u32(smem);
    const int tid  = threadIdx.x;
    const int lane = tid & 31;
    const int w    = tid >> 5;
    const int wm   = w >> 2;            // 0..1
    const int wn   = w & 3;             // 0..3
    const int g    = lane >> 2;
    const int t4   = lane & 3;
    const int m0   = blockIdx.x << 7;

    __shared__ float b11s[128];
    if (tid < 128) b11s[tid] = b11[tid];

    float acc[4][4][4];
#pragma unroll
    for (int a = 0; a < 4; ++a)
#pragma unroll
        for (int b = 0; b < 4; ++b)
#pragma unroll
            for (int c = 0; c < 4; ++c) acc[a][b][c] = 0.f;

    const int lrow = tid >> 2, lch = tid & 3;

    auto issue = [&](int s) {
        const int kk0 = (s & 3) << 5;
        const __half* Asrc = (s >= 4) ? g_Al : g_Ah;   // s 0..3: a1, 4..7: a2
        uint32_t base = sb + (uint32_t)(s % 3) * FC11_STG;
#pragma unroll
        for (int i = 0; i < 2; ++i) {
            int row = lrow + (i << 6);
            cpasync16(base + row * APITCH + (lch << 4),
                      Asrc + (size_t)(m0 + row) * 192 + kk0 + (lch << 3));
        }
#pragma unroll
        for (int i = 0; i < 2; ++i) {
            int row = lrow + (i << 6);
            cpasync16(base + 10240 + row * APITCH + (lch << 4),
                      g_B11 + (size_t)row * 128 + kk0 + (lch << 3));
        }
        cpcommit();
    };

    issue(0); issue(1);

    for (int s = 0; s < 8; ++s) {
        if (s < 7) { cpwait<1>(); } else { cpwait<0>(); }
        __syncthreads();
        if (s + 2 < 8) issue(s + 2);

        const uint32_t Ab = sb + (uint32_t)(s % 3) * FC11_STG;
        const uint32_t Bb = Ab + 10240u;
#pragma unroll
        for (int ks = 0; ks < 2; ++ks) {
            const int kk = ks << 4;
            uint32_t a[4][4];
#pragma unroll
            for (int mt = 0; mt < 4; ++mt) {
                int row = wm * 64 + mt * 16 + (lane & 15);
                ldsm_x4(a[mt][0], a[mt][1], a[mt][2], a[mt][3],
                        Ab + row * APITCH + ((kk + ((lane >> 4) << 3)) << 1));
            }
#pragma unroll
            for (int np = 0; np < 2; ++np) {
                int n = wn * 32 + np * 16 + ((lane >> 4) << 3) + (lane & 7);
                uint32_t b0, b1, b2, b3;
                ldsm_x4(b0, b1, b2, b3, Bb + n * APITCH + ((kk + (lane & 8)) << 1));
#pragma unroll
                for (int mt = 0; mt < 4; ++mt) {
                    mma16816(acc[mt][2*np][0], acc[mt][2*np][1], acc[mt][2*np][2], acc[mt][2*np][3],
                             a[mt][0], a[mt][1], a[mt][2], a[mt][3], b0, b1);
                    mma16816(acc[mt][2*np+1][0], acc[mt][2*np+1][1], acc[mt][2*np+1][2], acc[mt][2*np+1][3],
                             a[mt][0], a[mt][1], a[mt][2], a[mt][3], b2, b3);
                }
            }
        }
    }

    // epilogue: fragments hold (even,odd) col pairs -> dnew directly
#pragma unroll
    for (int mt = 0; mt < 4; ++mt)
#pragma unroll
        for (int nn = 0; nn < 4; ++nn) {
            int n = wn * 32 + (nn >> 1) * 16 + (nn & 1) * 8 + 2 * t4;
            float be = b11s[n], bo = b11s[n + 1];
            int r0 = m0 + wm * 64 + mt * 16 + g;
#pragma unroll
            for (int hh = 0; hh < 2; ++hh) {
                float v0 = acc[mt][nn][2 * hh]     + be;
                float v1 = acc[mt][nn][2 * hh + 1] + bo;
                v0 = v0 > 0.f ? v0 : 0.01f * v0;
                v1 = v1 > 0.f ? v1 : 0.01f * v1;
                float jn = fmaxf(v0, 0.f);
                float delta = sqrtf(jn * jn + v1 * v1 + 1e-12f);
                float dn = __fdividef(0.1f * (delta - 0.01f),
                                      fmaxf(delta, 1e-12f) * 0.09f);
                dn = fminf(fmaxf(dn, 0.f), 1.f);
                g_dnew[(size_t)(r0 + 8 * hh) * 64 + (n >> 1)] = dn;
            }
        }
}

// ---------------------------------------------------------------------------
// Kernel B: prefix-max of dnew over T -> dmg fp16 a1/a2 cols [128,192)
// ---------------------------------------------------------------------------
__global__ void k_prefixmax()
{
    int t = blockIdx.x * blockDim.x + threadIdx.x;   // 0..16383
    int b = t >> 6, p = t & 63;
    const float* src = g_dnew + (size_t)b * 512 * 64 + p;
    __half* dh = g_Ah + (size_t)b * 512 * 192 + 128 + p;
    __half* dl = g_Al + (size_t)b * 512 * 192 + 128 + p;
    float run = 0.f;
    for (int t0 = 0; t0 < 512; t0 += 8) {
        float v[8];
#pragma unroll
        for (int i = 0; i < 8; ++i) v[i] = src[(size_t)(t0 + i) * 64];
#pragma unroll
        for (int i = 0; i < 8; ++i) {
            run = fmaxf(run, v[i]);
            __half hi = __float2half(run);
            dh[(size_t)(t0 + i) * 192] = hi;
            dl[(size_t)(t0 + i) * 192] = __float2half(run - __half2float(hi));
        }
    }
}

// ---------------------------------------------------------------------------
// Kernel C: fc12 mma.sync GEMM. grid (1024,4): BM=128, BN=96, K'=384 (12 stages).
//   3-stage cp.async, 256 thr, warp grid 4Mx2N: warp tile 32x48, 2 CTA/SM.
//   Direct fragment stores (sig_tr only; seq computed in tail).
// ---------------------------------------------------------------------------
#define FC12_STG  17920
#define FC12_SMEM 53760

__global__ void __launch_bounds__(256, 2) k_fc12_mma()
{
    extern __shared__ char smem[];
    const uint32_t sb = smem_u32(smem);
    const int tid  = threadIdx.x;
    const int lane = tid & 31;
    const int w    = tid >> 5;
    const int wm   = w >> 1;
    const int wn   = w & 1;
    const int g    = lane >> 2;
    const int t4   = lane & 3;
    const int m0   = blockIdx.x << 7;
    const int gy   = blockIdx.y;          // n-tile: cols gy*96..

    float acc[2][6][4];
#pragma unroll
    for (int a = 0; a < 2; ++a)
#pragma unroll
        for (int b = 0; b < 6; ++b)
#pragma unroll
            for (int c = 0; c < 4; ++c) acc[a][b][c] = 0.f;

    const int lrow = tid >> 2, lch = tid & 3;

    auto issue = [&](int s) {
        const int kk0 = (s % 6) << 5;
        const __half* Asrc = (s >= 6) ? g_Al : g_Ah;   // s 0..5: a1, 6..11: a2
        uint32_t base = sb + (uint32_t)(s % 3) * FC12_STG;
#pragma unroll
        for (int i = 0; i < 2; ++i) {
            int row = lrow + (i << 6);
            cpasync16(base + row * APITCH + (lch << 4),
                      Asrc + (size_t)(m0 + row) * 192 + kk0 + (lch << 3));
        }
#pragma unroll
        for (int i = 0; i < 2; ++i) {
            int id = tid + (i << 8);
            if (id < 384) {
                int row = id >> 2, c = id & 3;
                cpasync16(base + 10240 + row * APITCH + (c << 4),
                          g_Bp + (size_t)(gy * 96 + row) * 192 + kk0 + (c << 3));
            }
        }
        cpcommit();
    };

    issue(0); issue(1);

    for (int s = 0; s < 12; ++s) {
        if (s < 11) { cpwait<1>(); } else { cpwait<0>(); }
        __syncthreads();
        if (s + 2 < 12) issue(s + 2);

        const uint32_t Ab = sb + (uint32_t)(s % 3) * FC12_STG;
        const uint32_t Bb = Ab + 10240u;
#pragma unroll
        for (int ks = 0; ks < 2; ++ks) {
            const int kk = ks << 4;
            uint32_t a[2][4];
#pragma unroll
            for (int mt = 0; mt < 2; ++mt) {
                int row = wm * 32 + mt * 16 + (lane & 15);
                ldsm_x4(a[mt][0], a[mt][1], a[mt][2], a[mt][3],
                        Ab + row * APITCH + ((kk + ((lane >> 4) << 3)) << 1));
            }
#pragma unroll
            for (int np = 0; np < 3; ++np) {
                int n = wn * 48 + np * 16 + ((lane >> 4) << 3) + (lane & 7);
                uint32_t b0, b1, b2, b3;
                ldsm_x4(b0, b1, b2, b3, Bb + n * APITCH + ((kk + (lane & 8)) << 1));
#pragma unroll
                for (int mt = 0; mt < 2; ++mt) {
                    mma16816(acc[mt][2*np][0], acc[mt][2*np][1], acc[mt][2*np][2], acc[mt][2*np][3],
                             a[mt][0], a[mt][1], a[mt][2], a[mt][3], b0, b1);
                    mma16816(acc[mt][2*np+1][0], acc[mt][2*np+1][1], acc[mt][2*np+1][2], acc[mt][2*np+1][3],
                             a[mt][0], a[mt][1], a[mt][2], a[mt][3], b2, b3);
                }
            }
        }
    }

    // direct fragment stores
    const int cb = gy * 96 + wn * 48;
#pragma unroll
    for (int mt = 0; mt < 2; ++mt) {
        int row0 = m0 + wm * 32 + mt * 16 + g;
#pragma unroll
        for (int j = 0; j < 6; ++j) {
            int col = cb + (j >> 1) * 16 + (j & 1) * 8 + 2 * t4;
            float2 vlo = make_float2(acc[mt][j][0], acc[mt][j][1]);
            float2 vhi = make_float2(acc[mt][j][2], acc[mt][j][3]);
            *(float2*)&g_strain[(size_t)row0 * 384 + col]       = vlo;
            *(float2*)&g_strain[(size_t)(row0 + 8) * 384 + col] = vhi;
        }
    }
}

// ---------------------------------------------------------------------------
// Kernel T: fused tail. One CTA per batch b (256 CTAs, 128 threads).
//   Per 32-t chunk: (1) cooperative load sig[32,384] -> smem,
//   (2) per-point seq + J2 radial-return chain + scale, in place,
//   (3) [32,384]x[384,6] GEMV + softplus -> out.
// ---------------------------------------------------------------------------
#define TAIL_SMEM (12288 + 49664)   // w2t [384][8] f32 + gs [32][388] f32

__global__ void __launch_bounds__(128, 3) k_tail(const float* __restrict__ W2,
                                                 float* __restrict__ out)
{
    extern __shared__ float ts[];
    float* w2t = ts;            // [384][8]
    float* gs  = ts + 3072;     // [32][388]
    const int tid = threadIdx.x;
    const int b   = blockIdx.x;

    for (int i = tid; i < 2304; i += 128) {
        int o = i / 384, k = i - o * 384;
        w2t[k * 8 + o] = W2[i];
    }

    const float SY = 10.f, H = 100.f;
    const float INV = (float)(1.0 / (3.0 * (1000.0 / 2.6) + 100.0));
    float ep = 0.f;
    const float* sigb = g_strain + (size_t)b * 512 * 384;
    const int tlb = tid >> 2, q = tid & 3;
    const int p = tid;

    for (int chunk = 0; chunk < 16; ++chunk) {
        __syncthreads();
        const float* src = sigb + (size_t)chunk * 32 * 384;
        for (int i = tid; i < 32 * 96; i += 128) {
            int tl = i / 96, c4 = i - tl * 96;
            *(float4*)&gs[tl * 388 + (c4 << 2)] = *(const float4*)(src + tl * 384 + (c4 << 2));
        }
        __syncthreads();
#pragma unroll 4
        for (int tl = 0; tl < 32; ++tl) {
            float* row = gs + tl * 388 + 3 * p;
            float s0 = row[0], s1 = row[1], s2 = row[2];
            float seq = sqrtf(s0 * s0 - s0 * s1 + s1 * s1 + 3.f * s2 * s2 + 1e-12f);
            float fy = seq - fmaf(H, ep, SY);
            float sc;
            if (fy > 0.f) {
                ep = fmaf(fy, INV, ep);
                sc = __fdividef(fmaf(H, ep, SY), seq);
            } else {
                sc = 1.f;
            }
            row[0] = sc * s0; row[1] = sc * s1; row[2] = sc * s2;
        }
        __syncthreads();
        float acc[6] = {0.f, 0.f, 0.f, 0.f, 0.f, 0.f};
        const float* grow = gs + tlb * 388;
#pragma unroll 8
        for (int i = 0; i < 96; ++i) {
            int k = (i << 2) + q;
            float gv = grow[k];
            float4 wa = *(float4*)&w2t[k * 8];
            float2 wb = *(float2*)&w2t[k * 8 + 4];
            acc[0] = fmaf(gv, wa.x, acc[0]);
            acc[1] = fmaf(gv, wa.y, acc[1]);
            acc[2] = fmaf(gv, wa.z, acc[2]);
            acc[3] = fmaf(gv, wa.w, acc[3]);
            acc[4] = fmaf(gv, wb.x, acc[4]);
            acc[5] = fmaf(gv, wb.y, acc[5]);
        }
#pragma unroll
        for (int o = 0; o < 6; ++o) {
            acc[o] += __shfl_xor_sync(0xffffffffu, acc[o], 1);
            acc[o] += __shfl_xor_sync(0xffffffffu, acc[o], 2);
        }
        if (q == 0) {
            int t = chunk * 32 + tlb;
            float* op = out + ((size_t)b * 512 + t) * 6;
#pragma unroll
            for (int o = 0; o < 6; ++o) {
                float v = acc[o];
                op[o] = fmaxf(v, 0.f) + log1pf(expf(-fabsf(v)));
            }
        }
    }
}

// ---------------------------------------------------------------------------
extern "C" void kernel_launch(void* const* d_in, const int* in_sizes, int n_in,
                              void* d_out, int out_size)
{
    const float* x   = (const float*)d_in[0];
    const float* W11 = (const float*)d_in[1];
    const float* b11 = (const float*)d_in[2];
    const float* W12 = (const float*)d_in[3];
    const float* W2  = (const float*)d_in[4];
    float* out = (float*)d_out;

    (void)in_sizes; (void)n_in; (void)out_size;

    cudaFuncSetAttribute(k_fc11_mma, cudaFuncAttributeMaxDynamicSharedMemorySize, FC11_SMEM);
    cudaFuncSetAttribute(k_fc12_mma, cudaFuncAttributeMaxDynamicSharedMemorySize, FC12_SMEM);
    cudaFuncSetAttribute(k_tail,     cudaFuncAttributeMaxDynamicSharedMemorySize, TAIL_SMEM);

    k_splitx<<<MM / 8, 256>>>(x);
    k_prepB11<<<64, 256>>>(W11);
    k_prepB<<<288, 256>>>(W12);
    k_fc11_mma<<<MM / 128, 256, FC11_SMEM>>>(b11);
    k_prefixmax<<<64, 256>>>();
    k_fc12_mma<<<dim3(MM / 128, 4), 256, FC12_SMEM>>>();
    k_tail<<<256, 128, TAIL_SMEM>>>(W2, out);
}